// round 1
// baseline (speedup 1.0000x reference)
#include <cuda_runtime.h>
#include <cuda_bf16.h>

#define Bdim 64
#define Sdim 48
#define MMAX 24
#define KD   25
#define Vdim 2048

// global scratch accumulator (allocation-free per harness rules)
__device__ double g_sum;

__global__ void ce_zero_kernel() {
    if (threadIdx.x == 0) g_sum = 0.0;
}

__global__ __launch_bounds__(256) void ce_row_kernel(
    const int*   __restrict__ labels,     // [B,S,MMAX]
    const float* __restrict__ logits,     // [B,S,K,V]
    const int*   __restrict__ seqlen,     // [B]
    const int*   __restrict__ mlen,       // [B,S]
    const int*   __restrict__ endtok)     // [1] or null
{
    const int k = blockIdx.x;
    const int s = blockIdx.y;
    const int b = blockIdx.z;

    // cheap validity check BEFORE touching the 8KB logits row
    if (s >= seqlen[b]) return;
    const int m = mlen[b * Sdim + s];
    if (k > m) return;

    const int et  = endtok ? endtok[0] : (Vdim - 1);
    const int lab = (k == m) ? et : labels[(b * Sdim + s) * MMAX + k];

    const float4* row = (const float4*)(logits +
        (((size_t)(b * Sdim + s)) * KD + k) * (size_t)Vdim);

    const int t = threadIdx.x;
    float4 a = row[t];
    float4 c = row[t + 256];

    __shared__ float s_xlab;
    {
        const int f4 = lab >> 2, cmp = lab & 3;
        if (f4 == t) {
            const float* p = (const float*)&a; s_xlab = p[cmp];
        } else if (f4 == t + 256) {
            const float* p = (const float*)&c; s_xlab = p[cmp];
        }
    }

    // block max
    float mx = fmaxf(fmaxf(fmaxf(a.x, a.y), fmaxf(a.z, a.w)),
                     fmaxf(fmaxf(c.x, c.y), fmaxf(c.z, c.w)));
    #pragma unroll
    for (int off = 16; off; off >>= 1)
        mx = fmaxf(mx, __shfl_xor_sync(0xffffffffu, mx, off));

    __shared__ float smax[8];
    const int w = t >> 5, l = t & 31;
    if (l == 0) smax[w] = mx;
    __syncthreads();
    const float bm = fmaxf(fmaxf(fmaxf(smax[0], smax[1]), fmaxf(smax[2], smax[3])),
                           fmaxf(fmaxf(smax[4], smax[5]), fmaxf(smax[6], smax[7])));

    // block sum of exp
    float sum = __expf(a.x - bm) + __expf(a.y - bm) + __expf(a.z - bm) + __expf(a.w - bm)
              + __expf(c.x - bm) + __expf(c.y - bm) + __expf(c.z - bm) + __expf(c.w - bm);
    #pragma unroll
    for (int off = 16; off; off >>= 1)
        sum += __shfl_xor_sync(0xffffffffu, sum, off);

    __shared__ float ssum[8];
    if (l == 0) ssum[w] = sum;
    __syncthreads();

    if (t == 0) {
        const float tot = ssum[0] + ssum[1] + ssum[2] + ssum[3]
                        + ssum[4] + ssum[5] + ssum[6] + ssum[7];
        const float nll = __logf(tot) + bm - s_xlab;
        atomicAdd(&g_sum, (double)nll);
    }
}

__global__ __launch_bounds__(256) void ce_finalize_kernel(
    const int* __restrict__ seqlen,
    const int* __restrict__ mlen,
    float* __restrict__ out)
{
    __shared__ int sc[256];
    const int t = threadIdx.x;
    int cnt = 0;
    for (int i = t; i < Bdim * Sdim; i += 256) {
        const int b = i / Sdim, s = i % Sdim;
        if (s < seqlen[b]) cnt += mlen[i] + 1;
    }
    sc[t] = cnt;
    __syncthreads();
    #pragma unroll
    for (int st = 128; st; st >>= 1) {
        if (t < st) sc[t] += sc[t + st];
        __syncthreads();
    }
    if (t == 0) out[0] = (float)(g_sum / (double)sc[0]);
}

extern "C" void kernel_launch(void* const* d_in, const int* in_sizes, int n_in,
                              void* d_out, int out_size) {
    const int*   labels = (const int*)  d_in[0];
    const float* logits = (const float*)d_in[1];
    const int*   seqlen = (const int*)  d_in[2];
    const int*   mlen   = (const int*)  d_in[3];
    const int*   endtok = (n_in > 5) ? (const int*)d_in[5] : nullptr;
    float* out = (float*)d_out;

    ce_zero_kernel<<<1, 32>>>();
    dim3 grid(KD, Sdim, Bdim);
    ce_row_kernel<<<grid, 256>>>(labels, logits, seqlen, mlen, endtok);
    ce_finalize_kernel<<<1, 256>>>(seqlen, mlen, out);
}

// round 2
// speedup vs baseline: 1.2886x; 1.2886x over previous
#include <cuda_runtime.h>
#include <cuda_bf16.h>

#define Bdim 64
#define Sdim 48
#define MMAX 24
#define KD   25
#define Vdim 2048
#define NROWS (Bdim * Sdim * KD)   // 76800

// per-row nll scratch; every block writes its own slot each launch -> deterministic
__device__ float g_nll[NROWS];

__global__ __launch_bounds__(256) void ce_row_kernel(
    const int*   __restrict__ labels,     // [B,S,MMAX]
    const float* __restrict__ logits,     // [B,S,K,V]
    const int*   __restrict__ seqlen,     // [B]
    const int*   __restrict__ mlen,       // [B,S]
    const int*   __restrict__ endtok)     // [1] or null
{
    const int k = blockIdx.x;
    const int s = blockIdx.y;
    const int b = blockIdx.z;
    const int row_idx = (b * Sdim + s) * KD + k;

    // cheap validity check BEFORE touching the 8KB logits row
    if (s >= seqlen[b]) {
        if (threadIdx.x == 0) g_nll[row_idx] = 0.0f;
        return;
    }
    const int m = mlen[b * Sdim + s];
    if (k > m) {
        if (threadIdx.x == 0) g_nll[row_idx] = 0.0f;
        return;
    }

    const int et  = endtok ? endtok[0] : (Vdim - 1);
    const int lab = (k == m) ? et : labels[(b * Sdim + s) * MMAX + k];

    const float4* row = (const float4*)(logits +
        (size_t)row_idx * (size_t)Vdim);

    const int t = threadIdx.x;
    float4 a = row[t];
    float4 c = row[t + 256];

    __shared__ float s_xlab;
    {
        const int f4 = lab >> 2, cmp = lab & 3;
        if (f4 == t) {
            const float* p = (const float*)&a; s_xlab = p[cmp];
        } else if (f4 == t + 256) {
            const float* p = (const float*)&c; s_xlab = p[cmp];
        }
    }

    // block max
    float mx = fmaxf(fmaxf(fmaxf(a.x, a.y), fmaxf(a.z, a.w)),
                     fmaxf(fmaxf(c.x, c.y), fmaxf(c.z, c.w)));
    #pragma unroll
    for (int off = 16; off; off >>= 1)
        mx = fmaxf(mx, __shfl_xor_sync(0xffffffffu, mx, off));

    __shared__ float smax[8];
    const int w = t >> 5, l = t & 31;
    if (l == 0) smax[w] = mx;
    __syncthreads();
    const float bm = fmaxf(fmaxf(fmaxf(smax[0], smax[1]), fmaxf(smax[2], smax[3])),
                           fmaxf(fmaxf(smax[4], smax[5]), fmaxf(smax[6], smax[7])));

    // block sum of exp
    float sum = __expf(a.x - bm) + __expf(a.y - bm) + __expf(a.z - bm) + __expf(a.w - bm)
              + __expf(c.x - bm) + __expf(c.y - bm) + __expf(c.z - bm) + __expf(c.w - bm);
    #pragma unroll
    for (int off = 16; off; off >>= 1)
        sum += __shfl_xor_sync(0xffffffffu, sum, off);

    __shared__ float ssum[8];
    if (l == 0) ssum[w] = sum;
    __syncthreads();

    if (t == 0) {
        const float tot = ssum[0] + ssum[1] + ssum[2] + ssum[3]
                        + ssum[4] + ssum[5] + ssum[6] + ssum[7];
        g_nll[row_idx] = __logf(tot) + bm - s_xlab;
    }
}

__global__ __launch_bounds__(1024) void ce_finalize_kernel(
    const int* __restrict__ seqlen,
    const int* __restrict__ mlen,
    float* __restrict__ out)
{
    const int t = threadIdx.x;

    // sum nll (float4-vectorized, ~19 iters/thread, MLP-covered)
    float sum = 0.0f;
    const float4* p = (const float4*)g_nll;
    #pragma unroll 4
    for (int i = t; i < NROWS / 4; i += 1024) {
        float4 v = p[i];
        sum += (v.x + v.y) + (v.z + v.w);
    }

    // analytic count
    int cnt = 0;
    for (int i = t; i < Bdim * Sdim; i += 1024) {
        const int b = i / Sdim, s = i % Sdim;
        if (s < seqlen[b]) cnt += mlen[i] + 1;
    }

    // block reduce both
    #pragma unroll
    for (int off = 16; off; off >>= 1) {
        sum += __shfl_xor_sync(0xffffffffu, sum, off);
        cnt += __shfl_xor_sync(0xffffffffu, cnt, off);
    }
    __shared__ float ss[32];
    __shared__ int   sc[32];
    const int w = t >> 5, l = t & 31;
    if (l == 0) { ss[w] = sum; sc[w] = cnt; }
    __syncthreads();
    if (w == 0) {
        float s2 = ss[l];
        int   c2 = sc[l];
        #pragma unroll
        for (int off = 16; off; off >>= 1) {
            s2 += __shfl_xor_sync(0xffffffffu, s2, off);
            c2 += __shfl_xor_sync(0xffffffffu, c2, off);
        }
        if (l == 0) out[0] = s2 / (float)c2;
    }
}

extern "C" void kernel_launch(void* const* d_in, const int* in_sizes, int n_in,
                              void* d_out, int out_size) {
    const int*   labels = (const int*)  d_in[0];
    const float* logits = (const float*)d_in[1];
    const int*   seqlen = (const int*)  d_in[2];
    const int*   mlen   = (const int*)  d_in[3];
    const int*   endtok = (n_in > 5) ? (const int*)d_in[5] : nullptr;
    float* out = (float*)d_out;

    dim3 grid(KD, Sdim, Bdim);
    ce_row_kernel<<<grid, 256>>>(labels, logits, seqlen, mlen, endtok);
    ce_finalize_kernel<<<1, 1024>>>(seqlen, mlen, out);
}

// round 3
// speedup vs baseline: 2.5170x; 1.9533x over previous
#include <cuda_runtime.h>
#include <cuda_bf16.h>

#define Bdim 64
#define Sdim 48
#define MMAX 24
#define KD   25
#define Vdim 2048
#define NBS  (Bdim * Sdim)   // 3072

// per-(b,s) partial nll sums; every block writes its slot each launch
__device__ float g_bs[NBS];

__global__ __launch_bounds__(256) void ce_row_kernel(
    const int*   __restrict__ labels,     // [B,S,MMAX]
    const float* __restrict__ logits,     // [B,S,K,V]
    const int*   __restrict__ seqlen,     // [B]
    const int*   __restrict__ mlen,       // [B,S]
    const int*   __restrict__ endtok)     // [1] or null
{
    const int bs = blockIdx.x;            // 0..3071
    const int b  = bs / Sdim;
    const int s  = bs % Sdim;
    const int w  = threadIdx.x >> 5;
    const int l  = threadIdx.x & 31;

    __shared__ float warp_nll[8];

    float acc = 0.0f;

    if (s < seqlen[b]) {
        const int m  = mlen[bs];
        const int et = endtok ? endtok[0] : (Vdim - 1);
        const float4* base = (const float4*)(logits + (size_t)bs * KD * Vdim);

        for (int k = w; k <= m; k += 8) {
            const int lab = (k == m) ? et : labels[bs * MMAX + k];
            const float4* row = base + (size_t)k * (Vdim / 4);

            // 16 independent 16B loads per lane -> MLP=16, covers whole row
            float4 v[16];
            #pragma unroll
            for (int i = 0; i < 16; i++)
                v[i] = row[l + 32 * i];

            // extract logits[lab]: owner lane picks its component, broadcast
            const int f4 = lab >> 2;
            const int owner = f4 & 31, seg = f4 >> 5, comp = lab & 3;
            float xl = 0.0f;
            #pragma unroll
            for (int i = 0; i < 16; i++) {
                if (i == seg) {
                    xl = (comp == 0) ? v[i].x :
                         (comp == 1) ? v[i].y :
                         (comp == 2) ? v[i].z : v[i].w;
                }
            }
            xl = __shfl_sync(0xffffffffu, xl, owner);

            // warp max
            float mx = -3.4e38f;
            #pragma unroll
            for (int i = 0; i < 16; i++)
                mx = fmaxf(mx, fmaxf(fmaxf(v[i].x, v[i].y), fmaxf(v[i].z, v[i].w)));
            #pragma unroll
            for (int off = 16; off; off >>= 1)
                mx = fmaxf(mx, __shfl_xor_sync(0xffffffffu, mx, off));

            // warp sum of exp
            float sum = 0.0f;
            #pragma unroll
            for (int i = 0; i < 16; i++) {
                sum += __expf(v[i].x - mx) + __expf(v[i].y - mx)
                     + __expf(v[i].z - mx) + __expf(v[i].w - mx);
            }
            #pragma unroll
            for (int off = 16; off; off >>= 1)
                sum += __shfl_xor_sync(0xffffffffu, sum, off);

            acc += __logf(sum) + mx - xl;   // identical in all lanes
        }
    }

    if (l == 0) warp_nll[w] = acc;
    __syncthreads();
    if (threadIdx.x == 0) {
        float t = 0.0f;
        #pragma unroll
        for (int i = 0; i < 8; i++) t += warp_nll[i];
        g_bs[bs] = t;
    }
}

__global__ __launch_bounds__(1024) void ce_finalize_kernel(
    const int* __restrict__ seqlen,
    const int* __restrict__ mlen,
    float* __restrict__ out)
{
    const int t = threadIdx.x;

    float sum = 0.0f;
    int   cnt = 0;
    #pragma unroll
    for (int i = t; i < NBS; i += 1024) {
        sum += g_bs[i];
        const int b = i / Sdim, s = i % Sdim;
        if (s < seqlen[b]) cnt += mlen[i] + 1;
    }

    #pragma unroll
    for (int off = 16; off; off >>= 1) {
        sum += __shfl_xor_sync(0xffffffffu, sum, off);
        cnt += __shfl_xor_sync(0xffffffffu, cnt, off);
    }
    __shared__ float ss[32];
    __shared__ int   sc[32];
    const int w = t >> 5, l = t & 31;
    if (l == 0) { ss[w] = sum; sc[w] = cnt; }
    __syncthreads();
    if (w == 0) {
        float s2 = ss[l];
        int   c2 = sc[l];
        #pragma unroll
        for (int off = 16; off; off >>= 1) {
            s2 += __shfl_xor_sync(0xffffffffu, s2, off);
            c2 += __shfl_xor_sync(0xffffffffu, c2, off);
        }
        if (l == 0) out[0] = s2 / (float)c2;
    }
}

extern "C" void kernel_launch(void* const* d_in, const int* in_sizes, int n_in,
                              void* d_out, int out_size) {
    const int*   labels = (const int*)  d_in[0];
    const float* logits = (const float*)d_in[1];
    const int*   seqlen = (const int*)  d_in[2];
    const int*   mlen   = (const int*)  d_in[3];
    const int*   endtok = (n_in > 5) ? (const int*)d_in[5] : nullptr;
    float* out = (float*)d_out;

    ce_row_kernel<<<NBS, 256>>>(labels, logits, seqlen, mlen, endtok);
    ce_finalize_kernel<<<1, 1024>>>(seqlen, mlen, out);
}